// round 1
// baseline (speedup 1.0000x reference)
#include <cuda_runtime.h>
#include <cuda_bf16.h>

// ---------------------------------------------------------------------------
// System2Reasoner: sim = P @ M^T, top-k(50) softmax(tau=0.02) message passing,
// l2norm update, evidence-softmax global feature.
//
// Pipeline:
//   K0 convert : fp32 -> bf16 copies of patches + memory (device scratch)
//   K1 gemm    : bf16 HMMA 128x128 tiles, fused per-row top-4-per-64-col
//                candidate extraction into global scratch
//   K2 merge   : per patch row: pick approx-near-max candidates, exact fp32
//                rescore, exact softmax, message, l2norm -> updated rows
//   K3 global  : evidence softmax over 2048 rows, weighted sum, l2norm
// ---------------------------------------------------------------------------

#define M_PATCH 2048
#define N_MEM   100000
#define D_DIM   256
#define INV_TAU 50.0f

#define BM 128
#define BN 128
#define BK 32
#define NT_M (M_PATCH / BM)                 // 16
#define NT_N ((N_MEM + BN - 1) / BN)        // 782
#define NCH  (NT_N * 2)                     // 1564 chunks of 64 columns
#define TOPC 4
#define SSTR 40                             // smem row stride (bf16): 32 + 8 pad

// -------------------- device scratch (static, no allocs) -------------------
__device__ __nv_bfloat16 g_mem_bf16[(size_t)N_MEM * D_DIM];
__device__ __nv_bfloat16 g_patch_bf16[(size_t)M_PATCH * D_DIM];
__device__ float g_cval[(size_t)M_PATCH * NCH * TOPC];
__device__ int   g_cidx[(size_t)M_PATCH * NCH * TOPC];
__device__ float g_evidence[M_PATCH];

// -------------------- small helpers ----------------------------------------
__device__ __forceinline__ unsigned smem_u32(const void* p) {
    return (unsigned)__cvta_generic_to_shared(p);
}
__device__ __forceinline__ void cp_async16(unsigned dst, const void* src) {
    asm volatile("cp.async.ca.shared.global [%0], [%1], 16;\n" :: "r"(dst), "l"(src));
}
#define CP_COMMIT() asm volatile("cp.async.commit_group;\n" ::: "memory")
#define CP_WAIT(N)  asm volatile("cp.async.wait_group %0;\n" :: "n"(N) : "memory")

__device__ __forceinline__ void ldmatrix_x4(unsigned* d, unsigned addr) {
    asm volatile("ldmatrix.sync.aligned.m8n8.x4.shared.b16 {%0,%1,%2,%3}, [%4];\n"
                 : "=r"(d[0]), "=r"(d[1]), "=r"(d[2]), "=r"(d[3]) : "r"(addr));
}
__device__ __forceinline__ void mma16816(float* c, const unsigned* a, const unsigned* b) {
    asm volatile(
        "mma.sync.aligned.m16n8k16.row.col.f32.bf16.bf16.f32 "
        "{%0,%1,%2,%3}, {%4,%5,%6,%7}, {%8,%9}, {%0,%1,%2,%3};\n"
        : "+f"(c[0]), "+f"(c[1]), "+f"(c[2]), "+f"(c[3])
        : "r"(a[0]), "r"(a[1]), "r"(a[2]), "r"(a[3]), "r"(b[0]), "r"(b[1]));
}

__device__ __forceinline__ void insert4(float v, int id, float tv[4], int ti[4]) {
    if (v > tv[3]) {
        if (v > tv[0]) {
            tv[3]=tv[2]; ti[3]=ti[2]; tv[2]=tv[1]; ti[2]=ti[1];
            tv[1]=tv[0]; ti[1]=ti[0]; tv[0]=v;    ti[0]=id;
        } else if (v > tv[1]) {
            tv[3]=tv[2]; ti[3]=ti[2]; tv[2]=tv[1]; ti[2]=ti[1];
            tv[1]=v;     ti[1]=id;
        } else if (v > tv[2]) {
            tv[3]=tv[2]; ti[3]=ti[2]; tv[2]=v; ti[2]=id;
        } else {
            tv[3]=v; ti[3]=id;
        }
    }
}

// deterministic block reductions (fixed tree), 256 threads
__device__ __forceinline__ float block_max256(float v, float* s) {
    int t = threadIdx.x;
    s[t] = v; __syncthreads();
    #pragma unroll
    for (int off = 128; off > 0; off >>= 1) {
        if (t < off) s[t] = fmaxf(s[t], s[t + off]);
        __syncthreads();
    }
    float r = s[0]; __syncthreads();
    return r;
}
__device__ __forceinline__ float block_sum256(float v, float* s) {
    int t = threadIdx.x;
    s[t] = v; __syncthreads();
    #pragma unroll
    for (int off = 128; off > 0; off >>= 1) {
        if (t < off) s[t] = s[t] + s[t + off];
        __syncthreads();
    }
    float r = s[0]; __syncthreads();
    return r;
}

// -------------------- K0: fp32 -> bf16 --------------------------------------
__global__ void convert_kernel(const float* __restrict__ patches,
                               const float* __restrict__ mem) {
    size_t stride = (size_t)gridDim.x * blockDim.x;
    size_t i0 = (size_t)blockIdx.x * blockDim.x + threadIdx.x;

    const float2* ms = (const float2*)mem;
    __nv_bfloat162* md = (__nv_bfloat162*)g_mem_bf16;
    size_t nm = (size_t)N_MEM * D_DIM / 2;
    for (size_t i = i0; i < nm; i += stride) md[i] = __float22bfloat162_rn(ms[i]);

    const float2* ps = (const float2*)patches;
    __nv_bfloat162* pd = (__nv_bfloat162*)g_patch_bf16;
    size_t np = (size_t)M_PATCH * D_DIM / 2;
    for (size_t i = i0; i < np; i += stride) pd[i] = __float22bfloat162_rn(ps[i]);
}

// -------------------- K1: GEMM + fused per-chunk top-4 ----------------------
// grid (NT_M, NT_N), 256 threads (8 warps as 4x2 M x N), warp tile 32x64
__global__ void __launch_bounds__(256)
gemm_topk_kernel() {
    __shared__ __nv_bfloat16 As[2][BM][SSTR];
    __shared__ __nv_bfloat16 Bs[2][BM][SSTR];

    const int m0 = blockIdx.x * BM;
    const int n0 = blockIdx.y * BN;
    const int tid  = threadIdx.x;
    const int warp = tid >> 5, lane = tid & 31;
    const int wx = warp >> 1, wy = warp & 1;      // wx: M quadrant, wy: N half
    const int g = lane >> 2, t = lane & 3;

    float acc[2][8][4];
    #pragma unroll
    for (int a = 0; a < 2; ++a)
        #pragma unroll
        for (int b = 0; b < 8; ++b)
            #pragma unroll
            for (int c = 0; c < 4; ++c) acc[a][b][c] = 0.0f;

    // loader: fill buffer buf with k-slab kstep
    auto load_tiles = [&](int buf, int kstep) {
        int k0 = kstep * BK;
        #pragma unroll
        for (int i = 0; i < 2; ++i) {
            int cid = tid + i * 256;          // 0..511
            int row = cid >> 2;               // 0..127
            int c4  = cid & 3;                // 16B chunk within 64B row
            // A (always in range: M=2048 divisible by 128)
            unsigned dA = smem_u32(&As[buf][row][c4 * 8]);
            cp_async16(dA, &g_patch_bf16[(size_t)(m0 + row) * D_DIM + k0 + c4 * 8]);
            // B (guard tail of N)
            int gn = n0 + row;
            if (gn < N_MEM) {
                unsigned dB = smem_u32(&Bs[buf][row][c4 * 8]);
                cp_async16(dB, &g_mem_bf16[(size_t)gn * D_DIM + k0 + c4 * 8]);
            } else {
                uint4 z = make_uint4(0, 0, 0, 0);
                *(uint4*)&Bs[buf][row][c4 * 8] = z;
            }
        }
    };

    const int KSTEPS = D_DIM / BK;            // 8
    load_tiles(0, 0); CP_COMMIT();

    for (int s = 0; s < KSTEPS; ++s) {
        if (s + 1 < KSTEPS) { load_tiles((s + 1) & 1, s + 1); CP_COMMIT(); CP_WAIT(1); }
        else                { CP_WAIT(0); }
        __syncthreads();

        int buf = s & 1;
        #pragma unroll
        for (int kk = 0; kk < BK; kk += 16) {
            unsigned afrag[2][4];
            #pragma unroll
            for (int mm = 0; mm < 2; ++mm) {
                int r = wx * 32 + mm * 16 + (lane & 15);
                int c = kk + ((lane >> 4) << 3);
                ldmatrix_x4(afrag[mm], smem_u32(&As[buf][r][c]));
            }
            unsigned bfrag[8][2];
            #pragma unroll
            for (int jp = 0; jp < 4; ++jp) {
                int r = wy * 64 + jp * 16 + (lane & 7) + ((lane >> 4) << 3);
                int c = kk + (((lane >> 3) & 1) << 3);
                unsigned q[4];
                ldmatrix_x4(q, smem_u32(&Bs[buf][r][c]));
                bfrag[2 * jp][0]     = q[0]; bfrag[2 * jp][1]     = q[1];
                bfrag[2 * jp + 1][0] = q[2]; bfrag[2 * jp + 1][1] = q[3];
            }
            #pragma unroll
            for (int mm = 0; mm < 2; ++mm)
                #pragma unroll
                for (int j = 0; j < 8; ++j)
                    mma16816(acc[mm][j], afrag[mm], bfrag[j]);
        }
        __syncthreads();
    }

    // ---- epilogue: per-row top-4 over this warp's 64 columns ----
    #pragma unroll
    for (int mm = 0; mm < 2; ++mm) {
        #pragma unroll
        for (int half = 0; half < 2; ++half) {
            float tv[4] = {-INFINITY, -INFINITY, -INFINITY, -INFINITY};
            int   ti[4] = {-1, -1, -1, -1};
            #pragma unroll
            for (int j = 0; j < 8; ++j) {
                #pragma unroll
                for (int c2 = 0; c2 < 2; ++c2) {
                    int gcol = n0 + wy * 64 + j * 8 + t * 2 + c2;
                    float v = acc[mm][j][half * 2 + c2];
                    if (gcol >= N_MEM) v = -INFINITY;
                    insert4(v, gcol, tv, ti);
                }
            }
            // merge across the quad (lanes 4g..4g+3 hold the same row)
            #pragma unroll
            for (int off = 1; off <= 2; off <<= 1) {
                float rv[4]; int ri[4];
                #pragma unroll
                for (int q = 0; q < 4; ++q) {
                    rv[q] = __shfl_xor_sync(0xffffffffu, tv[q], off);
                    ri[q] = __shfl_xor_sync(0xffffffffu, ti[q], off);
                }
                #pragma unroll
                for (int q = 0; q < 4; ++q) insert4(rv[q], ri[q], tv, ti);
            }
            if (t == 0) {
                int grow  = m0 + wx * 32 + mm * 16 + g + half * 8;
                int chunk = (n0 >> 6) + wy;
                size_t base = ((size_t)grow * NCH + chunk) * TOPC;
                #pragma unroll
                for (int q = 0; q < 4; ++q) {
                    g_cval[base + q] = tv[q];
                    g_cidx[base + q] = ti[q];
                }
            }
        }
    }
}

// -------------------- K2: merge + exact rescore + update --------------------
// one CTA (256 threads) per patch row
__global__ void __launch_bounds__(256)
merge_kernel(const float* __restrict__ patches,
             const float* __restrict__ mem,
             float* __restrict__ out) {
    const int row = blockIdx.x;
    const int tid = threadIdx.x;

    __shared__ float s_patch[D_DIM];
    __shared__ float s_red[256];
    __shared__ int   s_cnt[256];
    __shared__ int   s_sel[256];
    __shared__ float s_val[256];

    s_patch[tid] = patches[(size_t)row * D_DIM + tid];

    const float* cv = &g_cval[(size_t)row * NCH * TOPC];
    const int*   ci = &g_cidx[(size_t)row * NCH * TOPC];
    const int NC = NCH * TOPC;                       // 6256

    // approx max over candidates
    float mx = -INFINITY;
    for (int i = tid; i < NC; i += 256) mx = fmaxf(mx, cv[i]);
    float amax = block_max256(mx, s_red);
    float thr = amax - 1.2f;                         // covers exact window + bf16 noise

    // deterministic compaction of candidates >= thr
    int c = 0;
    for (int i = tid; i < NC; i += 256) if (cv[i] >= thr) c++;
    s_cnt[tid] = c; __syncthreads();
    for (int off = 1; off < 256; off <<= 1) {
        int v = (tid >= off) ? s_cnt[tid - off] : 0;
        __syncthreads();
        s_cnt[tid] += v;
        __syncthreads();
    }
    int total = s_cnt[255];
    int base = s_cnt[tid] - c;
    int nsel = min(total, 256);
    int o = base;
    for (int i = tid; i < NC; i += 256)
        if (cv[i] >= thr) { if (o < 256) s_sel[o] = ci[i]; o++; }
    __syncthreads();

    // exact fp32 rescore of selected candidates
    const int warp = tid >> 5, lane = tid & 31;
    for (int cs = warp; cs < nsel; cs += 8) {
        const float* mrow = mem + (size_t)s_sel[cs] * D_DIM;
        float ssum = 0.0f;
        #pragma unroll
        for (int d = lane; d < D_DIM; d += 32) ssum += mrow[d] * s_patch[d];
        #pragma unroll
        for (int off = 16; off > 0; off >>= 1)
            ssum += __shfl_xor_sync(0xffffffffu, ssum, off);
        if (lane == 0) s_val[cs] = ssum;
    }
    __syncthreads();

    // exact max (evidence) and softmax weights
    float vmx = -INFINITY;
    for (int i = tid; i < nsel; i += 256) vmx = fmaxf(vmx, s_val[i]);
    float vmax = block_max256(vmx, s_red);

    float zs = 0.0f;
    for (int i = tid; i < nsel; i += 256) {
        float w = expf((s_val[i] - vmax) * INV_TAU);
        s_val[i] = w;
        zs += w;
    }
    __syncthreads();
    float Z = block_sum256(zs, s_red);
    float Zinv = 1.0f / Z;

    // message for dimension tid
    float m = 0.0f;
    for (int cs = 0; cs < nsel; ++cs) {
        float w = s_val[cs];
        if (w > 0.0f) m += w * mem[(size_t)s_sel[cs] * D_DIM + tid];
    }
    float upd = s_patch[tid] + m * Zinv;

    float n2 = block_sum256(upd * upd, s_red);
    upd = upd / fmaxf(sqrtf(n2), 1e-12f);
    out[D_DIM + (size_t)row * D_DIM + tid] = upd;
    if (tid == 0) g_evidence[row] = vmax;
}

// -------------------- K3: global feature ------------------------------------
__global__ void __launch_bounds__(256)
global_kernel(float* __restrict__ out) {
    __shared__ float s_red[256];
    __shared__ float s_w[M_PATCH];
    const int tid = threadIdx.x;

    float mx = -INFINITY;
    for (int i = tid; i < M_PATCH; i += 256) mx = fmaxf(mx, g_evidence[i]);
    float emax = block_max256(mx, s_red);

    float zs = 0.0f;
    for (int i = tid; i < M_PATCH; i += 256) {
        float w = expf((g_evidence[i] - emax) * INV_TAU);
        s_w[i] = w;
        zs += w;
    }
    __syncthreads();
    float Z = block_sum256(zs, s_red);
    float Zinv = 1.0f / Z;

    float acc = 0.0f;
    for (int i = 0; i < M_PATCH; ++i) {
        float w = s_w[i];
        if (w > 0.0f) acc += w * out[D_DIM + (size_t)i * D_DIM + tid];
    }
    acc *= Zinv;

    float n2 = block_sum256(acc * acc, s_red);
    out[tid] = acc / fmaxf(sqrtf(n2), 1e-12f);
}

// -------------------- launcher ----------------------------------------------
extern "C" void kernel_launch(void* const* d_in, const int* in_sizes, int n_in,
                              void* d_out, int out_size) {
    const float* patches = (const float*)d_in[0];   // (2048, 256)
    const float* mem     = (const float*)d_in[1];   // (100000, 256)
    float* out = (float*)d_out;                     // [256 global | 2048*256 updated]

    convert_kernel<<<1024, 256>>>(patches, mem);
    dim3 grid(NT_M, NT_N);
    gemm_topk_kernel<<<grid, 256>>>();
    merge_kernel<<<M_PATCH, 256>>>(patches, mem, out);
    global_kernel<<<1, 256>>>(out);
}

// round 3
// speedup vs baseline: 2.2921x; 2.2921x over previous
#include <cuda_runtime.h>
#include <cstdint>

// ---------------------------------------------------------------------------
// System2Reasoner: sim = P @ M^T, top-k(50) softmax(tau=0.02) message passing,
// l2norm update, evidence-softmax global feature.
//
//   K0 quant  : fp32 -> int8 (fixed scale 127/6, saturating) for P and M
//   K1 gemm   : int8 IMMA m16n8k32, 128x128 CTA tile, K=256 in 4 cp.async
//               stages; fused per-row top-2-per-64-col candidate extraction
//   K2 merge  : per patch row: threshold candidates (window 3.2), exact fp32
//               rescore, exact softmax, message, l2norm -> updated rows
//   K3 G1/G2  : evidence softmax over 2048 rows, partial weighted sums
//               (32 CTAs) then reduce + l2norm (1 CTA)
//
// NOTE: tcgen05 is unusable here — the harness ptxas target is sm_100
// (no 'a' feature suffix), which rejects all tcgen05/TMEM instructions.
// ---------------------------------------------------------------------------

#define M_PATCH 2048
#define N_MEM   100000
#define D_DIM   256
#define INV_TAU 50.0f

#define BM 128
#define BN 128
#define BK 64
#define N_PAD 100096                        // 782 * 128
#define NT_M (M_PATCH / BM)                 // 16
#define NT_N (N_PAD / BN)                   // 782
#define NCH  (N_PAD / 64)                   // 1564 chunks of 64 columns
#define TOPC 2

#define QSCALE 21.166666f                   // 127/6
#define DEQ    0.0022320040f                // (6/127)^2
#define WINDOW 3.2f

// dynamic smem: A 4 stages x 8KB, then B 4 stages x 8KB
#define SMA_OFF 0
#define SMB_OFF 32768
#define SM_ALLOC 65536

// -------------------- device scratch (static, no allocs) -------------------
__device__ int8_t g_mem_s8[(size_t)N_PAD * D_DIM];     // pad rows stay 0
__device__ int8_t g_patch_s8[(size_t)M_PATCH * D_DIM];
__device__ float g_cval[(size_t)M_PATCH * NCH * TOPC];
__device__ int   g_cidx[(size_t)M_PATCH * NCH * TOPC];
__device__ float g_evidence[M_PATCH];
__device__ float g_part[32 * D_DIM];

// -------------------- PTX helpers ------------------------------------------
__device__ __forceinline__ unsigned smem_u32(const void* p) {
    return (unsigned)__cvta_generic_to_shared(p);
}
__device__ __forceinline__ void cp_async16(unsigned dst, const void* src) {
    asm volatile("cp.async.ca.shared.global [%0], [%1], 16;\n" :: "r"(dst), "l"(src));
}
#define CP_COMMIT() asm volatile("cp.async.commit_group;\n" ::: "memory")
#define CP_WAIT(N)  asm volatile("cp.async.wait_group %0;\n" :: "n"(N) : "memory")

__device__ __forceinline__ void ldmatrix_x4(unsigned* d, unsigned addr) {
    asm volatile("ldmatrix.sync.aligned.m8n8.x4.shared.b16 {%0,%1,%2,%3}, [%4];\n"
                 : "=r"(d[0]), "=r"(d[1]), "=r"(d[2]), "=r"(d[3]) : "r"(addr));
}
// int8 IMMA: D(s32 16x8) += A(s8 16x32) * B(s8 32x8)
__device__ __forceinline__ void imma16832(int* c, const unsigned* a, const unsigned* b) {
    asm volatile(
        "mma.sync.aligned.m16n8k32.row.col.s32.s8.s8.s32 "
        "{%0,%1,%2,%3}, {%4,%5,%6,%7}, {%8,%9}, {%0,%1,%2,%3};\n"
        : "+r"(c[0]), "+r"(c[1]), "+r"(c[2]), "+r"(c[3])
        : "r"(a[0]), "r"(a[1]), "r"(a[2]), "r"(a[3]), "r"(b[0]), "r"(b[1]));
}

// swizzled smem byte offset for row (0..127) of 64B, 16B-chunk c (0..3)
__device__ __forceinline__ unsigned swz(int row, int c) {
    return (unsigned)(row * 64 + ((c ^ ((row >> 1) & 3)) << 4));
}

// deterministic block reductions (fixed tree), 256 threads
__device__ __forceinline__ float block_max256(float v, float* s) {
    int t = threadIdx.x;
    s[t] = v; __syncthreads();
    #pragma unroll
    for (int off = 128; off > 0; off >>= 1) {
        if (t < off) s[t] = fmaxf(s[t], s[t + off]);
        __syncthreads();
    }
    float r = s[0]; __syncthreads();
    return r;
}
__device__ __forceinline__ float block_sum256(float v, float* s) {
    int t = threadIdx.x;
    s[t] = v; __syncthreads();
    #pragma unroll
    for (int off = 128; off > 0; off >>= 1) {
        if (t < off) s[t] = s[t] + s[t + off];
        __syncthreads();
    }
    float r = s[0]; __syncthreads();
    return r;
}

// -------------------- K0: fp32 -> int8 (fixed scale, saturating) ------------
__device__ __forceinline__ int8_t q8(float x) {
    float v = fminf(fmaxf(x * QSCALE, -127.0f), 127.0f);
    return (int8_t)__float2int_rn(v);
}
__global__ void quant_kernel(const float* __restrict__ patches,
                             const float* __restrict__ mem) {
    size_t stride = (size_t)gridDim.x * blockDim.x;
    size_t i0 = (size_t)blockIdx.x * blockDim.x + threadIdx.x;

    const float4* ms = (const float4*)mem;
    uchar4* md = (uchar4*)g_mem_s8;
    size_t nm = (size_t)N_MEM * D_DIM / 4;
    for (size_t i = i0; i < nm; i += stride) {
        float4 v = ms[i];
        uchar4 o;
        o.x = (uint8_t)q8(v.x); o.y = (uint8_t)q8(v.y);
        o.z = (uint8_t)q8(v.z); o.w = (uint8_t)q8(v.w);
        md[i] = o;
    }
    const float4* ps = (const float4*)patches;
    uchar4* pd = (uchar4*)g_patch_s8;
    size_t np = (size_t)M_PATCH * D_DIM / 4;
    for (size_t i = i0; i < np; i += stride) {
        float4 v = ps[i];
        uchar4 o;
        o.x = (uint8_t)q8(v.x); o.y = (uint8_t)q8(v.y);
        o.z = (uint8_t)q8(v.z); o.w = (uint8_t)q8(v.w);
        pd[i] = o;
    }
}

// -------------------- K1: int8 GEMM + fused top-2/64 ------------------------
// grid (NT_M, NT_N), 256 threads (8 warps: 4 M-quadrants x 2 N-halves),
// warp tile 32 (M) x 64 (N), K = 256 in 4 stages of 64.
__global__ void __launch_bounds__(256, 2)
gemm_topk_i8() {
    extern __shared__ char smem_raw[];
    const unsigned sa = smem_u32(smem_raw) + SMA_OFF;
    const unsigned sbb = smem_u32(smem_raw) + SMB_OFF;

    const int tid = threadIdx.x;
    const int warp = tid >> 5, lane = tid & 31;
    const int wx = warp >> 1, wy = warp & 1;
    const int g = lane >> 2, t = lane & 3;
    const int m0 = blockIdx.x * BM;
    const int n0 = blockIdx.y * BN;

    // issue all 4 K-stage loads (one commit group per stage)
    #pragma unroll
    for (int kc = 0; kc < 4; ++kc) {
        #pragma unroll
        for (int i = 0; i < 2; ++i) {
            int id = tid + i * 256;               // 0..511
            int row = id >> 2, c = id & 3;
            cp_async16(sa + kc * 8192 + swz(row, c),
                       &g_patch_s8[(size_t)(m0 + row) * D_DIM + kc * 64 + c * 16]);
            cp_async16(sbb + kc * 8192 + swz(row, c),
                       &g_mem_s8[(size_t)(n0 + row) * D_DIM + kc * 64 + c * 16]);
        }
        CP_COMMIT();
    }

    int acc[2][8][4];
    #pragma unroll
    for (int a = 0; a < 2; ++a)
        #pragma unroll
        for (int b = 0; b < 8; ++b)
            #pragma unroll
            for (int c = 0; c < 4; ++c) acc[a][b][c] = 0;

    #pragma unroll
    for (int kc = 0; kc < 4; ++kc) {
        if (kc == 0)      { CP_WAIT(3); }
        else if (kc == 1) { CP_WAIT(2); }
        else if (kc == 2) { CP_WAIT(1); }
        else              { CP_WAIT(0); }
        __syncthreads();

        #pragma unroll
        for (int kk = 0; kk < 2; ++kk) {          // two k=32 steps
            unsigned afrag[2][4];
            #pragma unroll
            for (int mm = 0; mm < 2; ++mm) {
                int r = wx * 32 + mm * 16 + (lane & 15);
                int c = kk * 2 + (lane >> 4);
                ldmatrix_x4(afrag[mm], sa + kc * 8192 + swz(r, c));
            }
            unsigned bfrag[8][2];
            #pragma unroll
            for (int jp = 0; jp < 4; ++jp) {
                int r = wy * 64 + jp * 16 + (lane & 7) + ((lane >> 4) << 3);
                int c = kk * 2 + ((lane >> 3) & 1);
                unsigned q[4];
                ldmatrix_x4(q, sbb + kc * 8192 + swz(r, c));
                bfrag[2 * jp][0]     = q[0]; bfrag[2 * jp][1]     = q[1];
                bfrag[2 * jp + 1][0] = q[2]; bfrag[2 * jp + 1][1] = q[3];
            }
            #pragma unroll
            for (int mm = 0; mm < 2; ++mm)
                #pragma unroll
                for (int j = 0; j < 8; ++j)
                    imma16832(acc[mm][j], afrag[mm], bfrag[j]);
        }
    }

    // ---- epilogue: per-row top-2 over this warp's 64 columns ----
    #pragma unroll
    for (int mm = 0; mm < 2; ++mm) {
        #pragma unroll
        for (int half = 0; half < 2; ++half) {
            float v0 = -INFINITY, v1 = -INFINITY;
            int   i0 = -1, i1 = -1;
            #pragma unroll
            for (int j = 0; j < 8; ++j) {
                #pragma unroll
                for (int c2 = 0; c2 < 2; ++c2) {
                    int col = n0 + wy * 64 + j * 8 + t * 2 + c2;
                    float v = (col < N_MEM) ? (float)acc[mm][j][half * 2 + c2] * DEQ
                                            : -INFINITY;
                    if (v > v0)      { v1 = v0; i1 = i0; v0 = v; i0 = col; }
                    else if (v > v1) { v1 = v;  i1 = col; }
                }
            }
            // merge across the quad (lanes 4g..4g+3 hold the same row)
            #pragma unroll
            for (int off = 1; off <= 2; off <<= 1) {
                float u0 = __shfl_xor_sync(0xffffffffu, v0, off);
                int  ui0 = __shfl_xor_sync(0xffffffffu, i0, off);
                float u1 = __shfl_xor_sync(0xffffffffu, v1, off);
                int  ui1 = __shfl_xor_sync(0xffffffffu, i1, off);
                if (u0 > v0) {
                    float s = v0; int si = i0;
                    v0 = u0; i0 = ui0;
                    if (u1 > s) { s = u1; si = ui1; }
                    v1 = s; i1 = si;
                } else if (u0 > v1) { v1 = u0; i1 = ui0; }
            }
            if (t == 0) {
                int grow  = m0 + wx * 32 + mm * 16 + g + half * 8;
                int chunk = (n0 >> 6) + wy;
                size_t base = ((size_t)grow * NCH + chunk) * TOPC;
                *(float2*)&g_cval[base] = make_float2(v0, v1);
                *(int2*)&g_cidx[base]   = make_int2(i0, i1);
            }
        }
    }
}

// -------------------- K2: merge + exact rescore + update --------------------
// one CTA (256 threads) per patch row
__global__ void __launch_bounds__(256)
merge_kernel(const float* __restrict__ patches,
             const float* __restrict__ mem,
             float* __restrict__ out) {
    const int row = blockIdx.x;
    const int tid = threadIdx.x;

    __shared__ float s_patch[D_DIM];
    __shared__ float s_red[256];
    __shared__ int   s_cnt[256];
    __shared__ int   s_sel[256];
    __shared__ float s_val[256];

    s_patch[tid] = patches[(size_t)row * D_DIM + tid];

    const float* cv = &g_cval[(size_t)row * NCH * TOPC];
    const int*   ci = &g_cidx[(size_t)row * NCH * TOPC];
    const int NC = NCH * TOPC;                       // 3128

    // approx (int8-screened) max over candidates
    float mx = -INFINITY;
    for (int i = tid; i < NC; i += 256) mx = fmaxf(mx, cv[i]);
    float amax = block_max256(mx, s_red);
    float thr = amax - WINDOW;

    // deterministic compaction of candidates >= thr
    int c = 0;
    for (int i = tid; i < NC; i += 256) if (cv[i] >= thr) c++;
    s_cnt[tid] = c; __syncthreads();
    for (int off = 1; off < 256; off <<= 1) {
        int v = (tid >= off) ? s_cnt[tid - off] : 0;
        __syncthreads();
        s_cnt[tid] += v;
        __syncthreads();
    }
    int total = s_cnt[255];
    int base = s_cnt[tid] - c;
    int nsel = min(total, 256);
    int o = base;
    for (int i = tid; i < NC; i += 256)
        if (cv[i] >= thr) { if (o < 256) s_sel[o] = ci[i]; o++; }
    __syncthreads();

    // exact fp32 rescore of selected candidates
    const int warp = tid >> 5, lane = tid & 31;
    for (int cs = warp; cs < nsel; cs += 8) {
        const float* mrow = mem + (size_t)s_sel[cs] * D_DIM;
        float ssum = 0.0f;
        #pragma unroll
        for (int d = lane; d < D_DIM; d += 32) ssum += mrow[d] * s_patch[d];
        #pragma unroll
        for (int off = 16; off > 0; off >>= 1)
            ssum += __shfl_xor_sync(0xffffffffu, ssum, off);
        if (lane == 0) s_val[cs] = ssum;
    }
    __syncthreads();

    // exact max (evidence) and softmax weights
    float vmx = -INFINITY;
    for (int i = tid; i < nsel; i += 256) vmx = fmaxf(vmx, s_val[i]);
    float vmax = block_max256(vmx, s_red);

    float zs = 0.0f;
    for (int i = tid; i < nsel; i += 256) {
        float w = expf((s_val[i] - vmax) * INV_TAU);
        s_val[i] = w;
        zs += w;
    }
    __syncthreads();
    float Z = block_sum256(zs, s_red);
    float Zinv = 1.0f / Z;

    // message for dimension tid
    float m = 0.0f;
    for (int cs = 0; cs < nsel; ++cs) {
        float w = s_val[cs];
        if (w > 0.0f) m += w * mem[(size_t)s_sel[cs] * D_DIM + tid];
    }
    float upd = s_patch[tid] + m * Zinv;

    float n2 = block_sum256(upd * upd, s_red);
    upd = upd / fmaxf(sqrtf(n2), 1e-12f);
    out[D_DIM + (size_t)row * D_DIM + tid] = upd;
    if (tid == 0) g_evidence[row] = vmax;
}

// -------------------- K3: global feature (two-phase, deterministic) ---------
__global__ void __launch_bounds__(256)
global_partial_kernel(const float* __restrict__ out) {
    __shared__ float s_red[256];
    const int tid = threadIdx.x;
    const int r0 = blockIdx.x * (M_PATCH / 32);      // 64 rows per CTA

    float mx = -INFINITY;
    for (int i = tid; i < M_PATCH; i += 256) mx = fmaxf(mx, g_evidence[i]);
    float emax = block_max256(mx, s_red);

    float zs = 0.0f;
    for (int i = tid; i < M_PATCH; i += 256) zs += expf((g_evidence[i] - emax) * INV_TAU);
    float Z = block_sum256(zs, s_red);
    float Zinv = 1.0f / Z;

    float acc = 0.0f;
    for (int r = 0; r < M_PATCH / 32; ++r) {
        int i = r0 + r;
        float w = expf((g_evidence[i] - emax) * INV_TAU);
        if (w > 0.0f) acc += w * out[D_DIM + (size_t)i * D_DIM + tid];
    }
    g_part[blockIdx.x * D_DIM + tid] = acc * Zinv;
}

__global__ void __launch_bounds__(256)
global_reduce_kernel(float* __restrict__ out) {
    __shared__ float s_red[256];
    const int tid = threadIdx.x;
    float acc = 0.0f;
    #pragma unroll
    for (int c = 0; c < 32; ++c) acc += g_part[c * D_DIM + tid];
    float n2 = block_sum256(acc * acc, s_red);
    out[tid] = acc / fmaxf(sqrtf(n2), 1e-12f);
}

// -------------------- launcher ----------------------------------------------
extern "C" void kernel_launch(void* const* d_in, const int* in_sizes, int n_in,
                              void* d_out, int out_size) {
    const float* patches = (const float*)d_in[0];   // (2048, 256)
    const float* mem     = (const float*)d_in[1];   // (100000, 256)
    float* out = (float*)d_out;                     // [256 global | 2048*256 updated]

    cudaFuncSetAttribute(gemm_topk_i8, cudaFuncAttributeMaxDynamicSharedMemorySize,
                         SM_ALLOC);

    quant_kernel<<<1024, 256>>>(patches, mem);
    dim3 grid(NT_M, NT_N);
    gemm_topk_i8<<<grid, 256, SM_ALLOC>>>();
    merge_kernel<<<M_PATCH, 256>>>(patches, mem, out);
    global_partial_kernel<<<32, 256>>>(out);
    global_reduce_kernel<<<1, 256>>>(out);
}

// round 4
// speedup vs baseline: 2.3985x; 1.0464x over previous
#include <cuda_runtime.h>
#include <cstdint>

// ---------------------------------------------------------------------------
// System2Reasoner: sim = P @ M^T, top-k(50) softmax(tau=0.02) message passing,
// l2norm update, evidence-softmax global feature.
//
//   K0 quant  : fp32 -> int8 (fixed scale 127/6, saturating), written PRE-TILED
//               and PRE-SWIZZLED (tile = 128 rows x 256 k, as 4 x 8KB blocks
//               that are byte-identical to the smem image)
//   K1 gemm   : int8 IMMA m16n8k32, 128x128 CTA tile, K=256; tiles filled with
//               cp.async.bulk (TMA path) instead of per-16B cp.async —
//               removes the LDGSTS issue-rate bottleneck (8cyc/op/SMSP);
//               fused per-row top-2-per-64-col candidate extraction
//   K2 merge  : per patch row: threshold candidates (window 3.2), exact fp32
//               rescore, exact softmax, message, l2norm -> updated rows
//   K3 G1/G2  : evidence softmax over 2048 rows, partial weighted sums
//               (128 CTAs) then reduce + l2norm (1 CTA)
//
// NOTE: tcgen05 is unusable here — the harness ptxas target is sm_100
// (no 'a' suffix). cp.async.bulk (1D) is baseline sm_90+ and compiles.
// ---------------------------------------------------------------------------

#define M_PATCH 2048
#define N_MEM   100000
#define D_DIM   256
#define INV_TAU 50.0f

#define BM 128
#define BN 128
#define N_PAD 100096                        // 782 * 128
#define NT_M (M_PATCH / BM)                 // 16
#define NT_N (N_PAD / BN)                   // 782
#define NCH  (N_PAD / 64)                   // 1564 chunks of 64 columns
#define TOPC 2
#define TILE_BYTES 32768                    // 128 rows x 256 k int8

#define QSCALE 21.166666f                   // 127/6
#define DEQ    0.0022320040f                // (6/127)^2
#define WINDOW 3.2f

#define PARTS 128

// dynamic smem: A tile 32KB, then B tile 32KB
#define SM_ALLOC 65536

// -------------------- device scratch (static, no allocs) -------------------
__device__ int8_t g_memT[(size_t)NT_N * TILE_BYTES];     // pre-tiled B
__device__ int8_t g_patchT[(size_t)NT_M * TILE_BYTES];   // pre-tiled A
__device__ float g_cval[(size_t)M_PATCH * NCH * TOPC];
__device__ int   g_cidx[(size_t)M_PATCH * NCH * TOPC];
__device__ float g_evidence[M_PATCH];
__device__ float g_part[PARTS * D_DIM];

// -------------------- PTX helpers ------------------------------------------
__device__ __forceinline__ unsigned smem_u32(const void* p) {
    return (unsigned)__cvta_generic_to_shared(p);
}
__device__ __forceinline__ void cp_bulk(unsigned dst, const void* src,
                                        unsigned bytes, unsigned mbar) {
    asm volatile(
        "cp.async.bulk.shared::cluster.global.mbarrier::complete_tx::bytes "
        "[%0], [%1], %2, [%3];"
        :: "r"(dst), "l"(src), "r"(bytes), "r"(mbar) : "memory");
}
#define MBARRIER_INIT(mbar, cnt) \
    asm volatile("mbarrier.init.shared.b64 [%0], %1;" \
                 :: "r"((uint32_t)(mbar)), "r"((uint32_t)(cnt)) : "memory")
#define MBARRIER_EXPECT_TX(mbar, bytes) \
    asm volatile("mbarrier.arrive.expect_tx.shared.b64 _, [%0], %1;" \
                 :: "r"((uint32_t)(mbar)), "r"((uint32_t)(bytes)) : "memory")
__device__ __forceinline__ void mbar_wait_parity(uint32_t mbar, uint32_t parity) {
    uint32_t done;
    asm volatile(
        "{\n\t.reg .pred p;\n\t"
        "mbarrier.try_wait.parity.acquire.cta.shared::cta.b64 p, [%1], %2;\n\t"
        "selp.b32 %0, 1, 0, p;\n\t}"
        : "=r"(done) : "r"(mbar), "r"(parity) : "memory");
    if (!done) {
        asm volatile(
            "{\n\t.reg .pred P1;\n\t"
            "WAIT_LOOP_%=:\n\t"
            "mbarrier.try_wait.parity.acquire.cta.shared::cta.b64 P1, [%0], %1, 0x989680;\n\t"
            "@P1 bra.uni WAIT_DONE_%=;\n\t"
            "bra.uni WAIT_LOOP_%=;\n\t"
            "WAIT_DONE_%=:\n\t}"
            :: "r"(mbar), "r"(parity) : "memory");
    }
}

__device__ __forceinline__ void ldmatrix_x4(unsigned* d, unsigned addr) {
    asm volatile("ldmatrix.sync.aligned.m8n8.x4.shared.b16 {%0,%1,%2,%3}, [%4];\n"
                 : "=r"(d[0]), "=r"(d[1]), "=r"(d[2]), "=r"(d[3]) : "r"(addr));
}
// int8 IMMA: D(s32 16x8) += A(s8 16x32) * B(s8 32x8)
__device__ __forceinline__ void imma16832(int* c, const unsigned* a, const unsigned* b) {
    asm volatile(
        "mma.sync.aligned.m16n8k32.row.col.s32.s8.s8.s32 "
        "{%0,%1,%2,%3}, {%4,%5,%6,%7}, {%8,%9}, {%0,%1,%2,%3};\n"
        : "+r"(c[0]), "+r"(c[1]), "+r"(c[2]), "+r"(c[3])
        : "r"(a[0]), "r"(a[1]), "r"(a[2]), "r"(a[3]), "r"(b[0]), "r"(b[1]));
}

// swizzled byte offset within an 8KB block: row (0..127) of 64B, 16B chunk c
__device__ __forceinline__ unsigned swz(int row, int c) {
    return (unsigned)(row * 64 + ((c ^ ((row >> 1) & 3)) << 4));
}

// deterministic block reductions (fixed tree), 256 threads
__device__ __forceinline__ float block_max256(float v, float* s) {
    int t = threadIdx.x;
    s[t] = v; __syncthreads();
    #pragma unroll
    for (int off = 128; off > 0; off >>= 1) {
        if (t < off) s[t] = fmaxf(s[t], s[t + off]);
        __syncthreads();
    }
    float r = s[0]; __syncthreads();
    return r;
}
__device__ __forceinline__ float block_sum256(float v, float* s) {
    int t = threadIdx.x;
    s[t] = v; __syncthreads();
    #pragma unroll
    for (int off = 128; off > 0; off >>= 1) {
        if (t < off) s[t] = s[t] + s[t + off];
        __syncthreads();
    }
    float r = s[0]; __syncthreads();
    return r;
}

// -------------------- K0: fp32 -> int8, pre-tiled + pre-swizzled ------------
__device__ __forceinline__ int8_t q8(float x) {
    float v = fminf(fmaxf(x * QSCALE, -127.0f), 127.0f);
    return (int8_t)__float2int_rn(v);
}
__device__ __forceinline__ uint32_t q8x4(float4 v) {
    uint32_t r;
    uint8_t b0 = (uint8_t)q8(v.x), b1 = (uint8_t)q8(v.y);
    uint8_t b2 = (uint8_t)q8(v.z), b3 = (uint8_t)q8(v.w);
    r = (uint32_t)b0 | ((uint32_t)b1 << 8) | ((uint32_t)b2 << 16) | ((uint32_t)b3 << 24);
    return r;
}
// one thread handles one 16B chunk: quantize 16 floats -> 16 bytes, store at
// tiled+swizzled position. rows >= nrows are zero-filled (pad).
__global__ void quant_kernel(const float* __restrict__ patches,
                             const float* __restrict__ mem) {
    size_t stride = (size_t)gridDim.x * blockDim.x;
    size_t i0 = (size_t)blockIdx.x * blockDim.x + threadIdx.x;

    const size_t nB = (size_t)N_PAD * 16;          // 16 chunks per 256-elem row
    for (size_t i = i0; i < nB; i += stride) {
        int n = (int)(i >> 4), w = (int)(i & 15);
        int kc = w >> 2, c = w & 3;
        uint4 o = make_uint4(0, 0, 0, 0);
        if (n < N_MEM) {
            const float4* src = (const float4*)&mem[(size_t)n * D_DIM + w * 16];
            o.x = q8x4(src[0]); o.y = q8x4(src[1]);
            o.z = q8x4(src[2]); o.w = q8x4(src[3]);
        }
        size_t dst = (size_t)(n >> 7) * TILE_BYTES + kc * 8192 + swz(n & 127, c);
        *(uint4*)&g_memT[dst] = o;
    }
    const size_t nA = (size_t)M_PATCH * 16;
    for (size_t i = i0; i < nA; i += stride) {
        int m = (int)(i >> 4), w = (int)(i & 15);
        int kc = w >> 2, c = w & 3;
        const float4* src = (const float4*)&patches[(size_t)m * D_DIM + w * 16];
        uint4 o;
        o.x = q8x4(src[0]); o.y = q8x4(src[1]);
        o.z = q8x4(src[2]); o.w = q8x4(src[3]);
        size_t dst = (size_t)(m >> 7) * TILE_BYTES + kc * 8192 + swz(m & 127, c);
        *(uint4*)&g_patchT[dst] = o;
    }
}

// -------------------- K1: int8 GEMM + fused top-2/64 ------------------------
// grid (NT_M, NT_N), 256 threads (8 warps: 4 M-quadrants x 2 N-halves),
// warp tile 32 (M) x 64 (N), K = 256. Tiles arrive via 2-stage cp.async.bulk.
__global__ void __launch_bounds__(256, 2)
gemm_topk_i8() {
    extern __shared__ char smem_raw[];
    const unsigned sa  = smem_u32(smem_raw);
    const unsigned sbb = sa + 32768;
    __shared__ alignas(8) unsigned long long mbars[2];
    const unsigned mb0 = smem_u32(&mbars[0]);
    const unsigned mb1 = smem_u32(&mbars[1]);

    const int tid = threadIdx.x;
    const int warp = tid >> 5, lane = tid & 31;
    const int wx = warp >> 1, wy = warp & 1;
    const int g = lane >> 2, t = lane & 3;
    const int m0 = blockIdx.x * BM;
    const int n0 = blockIdx.y * BN;

    if (tid == 0) { MBARRIER_INIT(mb0, 1); MBARRIER_INIT(mb1, 1); }
    __syncthreads();
    if (tid == 0) {
        const int8_t* Ab = &g_patchT[(size_t)blockIdx.x * TILE_BYTES];
        const int8_t* Bb = &g_memT[(size_t)blockIdx.y * TILE_BYTES];
        MBARRIER_EXPECT_TX(mb0, 32768);
        cp_bulk(sa, Ab, 16384, mb0);
        cp_bulk(sbb, Bb, 16384, mb0);
        MBARRIER_EXPECT_TX(mb1, 32768);
        cp_bulk(sa + 16384, Ab + 16384, 16384, mb1);
        cp_bulk(sbb + 16384, Bb + 16384, 16384, mb1);
    }

    int acc[2][8][4];
    #pragma unroll
    for (int a = 0; a < 2; ++a)
        #pragma unroll
        for (int b = 0; b < 8; ++b)
            #pragma unroll
            for (int c = 0; c < 4; ++c) acc[a][b][c] = 0;

    #pragma unroll
    for (int kc = 0; kc < 4; ++kc) {
        if (kc == 0) mbar_wait_parity(mb0, 0);
        if (kc == 2) mbar_wait_parity(mb1, 0);

        #pragma unroll
        for (int kk = 0; kk < 2; ++kk) {          // two k=32 steps
            unsigned afrag[2][4];
            #pragma unroll
            for (int mm = 0; mm < 2; ++mm) {
                int r = wx * 32 + mm * 16 + (lane & 15);
                int c = kk * 2 + (lane >> 4);
                ldmatrix_x4(afrag[mm], sa + kc * 8192 + swz(r, c));
            }
            unsigned bfrag[8][2];
            #pragma unroll
            for (int jp = 0; jp < 4; ++jp) {
                int r = wy * 64 + jp * 16 + (lane & 7) + ((lane >> 4) << 3);
                int c = kk * 2 + ((lane >> 3) & 1);
                unsigned q[4];
                ldmatrix_x4(q, sbb + kc * 8192 + swz(r, c));
                bfrag[2 * jp][0]     = q[0]; bfrag[2 * jp][1]     = q[1];
                bfrag[2 * jp + 1][0] = q[2]; bfrag[2 * jp + 1][1] = q[3];
            }
            #pragma unroll
            for (int mm = 0; mm < 2; ++mm)
                #pragma unroll
                for (int j = 0; j < 8; ++j)
                    imma16832(acc[mm][j], afrag[mm], bfrag[j]);
        }
    }

    // ---- epilogue: per-row top-2 over this warp's 64 columns ----
    #pragma unroll
    for (int mm = 0; mm < 2; ++mm) {
        #pragma unroll
        for (int half = 0; half < 2; ++half) {
            float v0 = -INFINITY, v1 = -INFINITY;
            int   i0 = -1, i1 = -1;
            #pragma unroll
            for (int j = 0; j < 8; ++j) {
                #pragma unroll
                for (int c2 = 0; c2 < 2; ++c2) {
                    int col = n0 + wy * 64 + j * 8 + t * 2 + c2;
                    float v = (col < N_MEM) ? (float)acc[mm][j][half * 2 + c2] * DEQ
                                            : -INFINITY;
                    if (v > v0)      { v1 = v0; i1 = i0; v0 = v; i0 = col; }
                    else if (v > v1) { v1 = v;  i1 = col; }
                }
            }
            // merge across the quad (lanes 4g..4g+3 hold the same row)
            #pragma unroll
            for (int off = 1; off <= 2; off <<= 1) {
                float u0 = __shfl_xor_sync(0xffffffffu, v0, off);
                int  ui0 = __shfl_xor_sync(0xffffffffu, i0, off);
                float u1 = __shfl_xor_sync(0xffffffffu, v1, off);
                int  ui1 = __shfl_xor_sync(0xffffffffu, i1, off);
                if (u0 > v0) {
                    float s = v0; int si = i0;
                    v0 = u0; i0 = ui0;
                    if (u1 > s) { s = u1; si = ui1; }
                    v1 = s; i1 = si;
                } else if (u0 > v1) { v1 = u0; i1 = ui0; }
            }
            if (t == 0) {
                int grow  = m0 + wx * 32 + mm * 16 + g + half * 8;
                int chunk = (n0 >> 6) + wy;
                size_t base = ((size_t)grow * NCH + chunk) * TOPC;
                *(float2*)&g_cval[base] = make_float2(v0, v1);
                *(int2*)&g_cidx[base]   = make_int2(i0, i1);
            }
        }
    }
}

// -------------------- K2: merge + exact rescore + update --------------------
// one CTA (256 threads) per patch row
__global__ void __launch_bounds__(256)
merge_kernel(const float* __restrict__ patches,
             const float* __restrict__ mem,
             float* __restrict__ out) {
    const int row = blockIdx.x;
    const int tid = threadIdx.x;

    __shared__ float s_patch[D_DIM];
    __shared__ float s_red[256];
    __shared__ int   s_cnt[256];
    __shared__ int   s_sel[256];
    __shared__ float s_val[256];

    s_patch[tid] = patches[(size_t)row * D_DIM + tid];

    const float* cv = &g_cval[(size_t)row * NCH * TOPC];
    const int*   ci = &g_cidx[(size_t)row * NCH * TOPC];
    const int NC = NCH * TOPC;                       // 3128

    // approx (int8-screened) max over candidates
    float mx = -INFINITY;
    for (int i = tid; i < NC; i += 256) mx = fmaxf(mx, cv[i]);
    float amax = block_max256(mx, s_red);
    float thr = amax - WINDOW;

    // deterministic compaction of candidates >= thr
    int c = 0;
    for (int i = tid; i < NC; i += 256) if (cv[i] >= thr) c++;
    s_cnt[tid] = c; __syncthreads();
    for (int off = 1; off < 256; off <<= 1) {
        int v = (tid >= off) ? s_cnt[tid - off] : 0;
        __syncthreads();
        s_cnt[tid] += v;
        __syncthreads();
    }
    int total = s_cnt[255];
    int base = s_cnt[tid] - c;
    int nsel = min(total, 256);
    int o = base;
    for (int i = tid; i < NC; i += 256)
        if (cv[i] >= thr) { if (o < 256) s_sel[o] = ci[i]; o++; }
    __syncthreads();

    // exact fp32 rescore of selected candidates
    const int warp = tid >> 5, lane = tid & 31;
    for (int cs = warp; cs < nsel; cs += 8) {
        const float* mrow = mem + (size_t)s_sel[cs] * D_DIM;
        float ssum = 0.0f;
        #pragma unroll
        for (int d = lane; d < D_DIM; d += 32) ssum += mrow[d] * s_patch[d];
        #pragma unroll
        for (int off = 16; off > 0; off >>= 1)
            ssum += __shfl_xor_sync(0xffffffffu, ssum, off);
        if (lane == 0) s_val[cs] = ssum;
    }
    __syncthreads();

    // exact max (evidence) and softmax weights
    float vmx = -INFINITY;
    for (int i = tid; i < nsel; i += 256) vmx = fmaxf(vmx, s_val[i]);
    float vmax = block_max256(vmx, s_red);

    float zs = 0.0f;
    for (int i = tid; i < nsel; i += 256) {
        float w = expf((s_val[i] - vmax) * INV_TAU);
        s_val[i] = w;
        zs += w;
    }
    __syncthreads();
    float Z = block_sum256(zs, s_red);
    float Zinv = 1.0f / Z;

    // message for dimension tid
    float m = 0.0f;
    for (int cs = 0; cs < nsel; ++cs) {
        float w = s_val[cs];
        if (w > 0.0f) m += w * mem[(size_t)s_sel[cs] * D_DIM + tid];
    }
    float upd = s_patch[tid] + m * Zinv;

    float n2 = block_sum256(upd * upd, s_red);
    upd = upd / fmaxf(sqrtf(n2), 1e-12f);
    out[D_DIM + (size_t)row * D_DIM + tid] = upd;
    if (tid == 0) g_evidence[row] = vmax;
}

// -------------------- K3: global feature (two-phase, deterministic) ---------
__global__ void __launch_bounds__(256)
global_partial_kernel(const float* __restrict__ out) {
    __shared__ float s_red[256];
    const int tid = threadIdx.x;
    const int r0 = blockIdx.x * (M_PATCH / PARTS);

    float mx = -INFINITY;
    for (int i = tid; i < M_PATCH; i += 256) mx = fmaxf(mx, g_evidence[i]);
    float emax = block_max256(mx, s_red);

    float zs = 0.0f;
    for (int i = tid; i < M_PATCH; i += 256) zs += expf((g_evidence[i] - emax) * INV_TAU);
    float Z = block_sum256(zs, s_red);
    float Zinv = 1.0f / Z;

    float acc = 0.0f;
    #pragma unroll
    for (int r = 0; r < M_PATCH / PARTS; ++r) {
        int i = r0 + r;
        float w = expf((g_evidence[i] - emax) * INV_TAU);
        if (w > 0.0f) acc += w * out[D_DIM + (size_t)i * D_DIM + tid];
    }
    g_part[blockIdx.x * D_DIM + tid] = acc * Zinv;
}

__global__ void __launch_bounds__(256)
global_reduce_kernel(float* __restrict__ out) {
    __shared__ float s_red[256];
    const int tid = threadIdx.x;
    float acc = 0.0f;
    #pragma unroll
    for (int c = 0; c < PARTS; ++c) acc += g_part[c * D_DIM + tid];
    float n2 = block_sum256(acc * acc, s_red);
    out[tid] = acc / fmaxf(sqrtf(n2), 1e-12f);
}

// -------------------- launcher ----------------------------------------------
extern "C" void kernel_launch(void* const* d_in, const int* in_sizes, int n_in,
                              void* d_out, int out_size) {
    const float* patches = (const float*)d_in[0];   // (2048, 256)
    const float* mem     = (const float*)d_in[1];   // (100000, 256)
    float* out = (float*)d_out;                     // [256 global | 2048*256 updated]

    cudaFuncSetAttribute(gemm_topk_i8, cudaFuncAttributeMaxDynamicSharedMemorySize,
                         SM_ALLOC);

    quant_kernel<<<2048, 256>>>(patches, mem);
    dim3 grid(NT_M, NT_N);
    gemm_topk_i8<<<grid, 256, SM_ALLOC>>>();
    merge_kernel<<<M_PATCH, 256>>>(patches, mem, out);
    global_partial_kernel<<<PARTS, 256>>>(out);
    global_reduce_kernel<<<1, 256>>>(out);
}

// round 5
// speedup vs baseline: 2.4274x; 1.0121x over previous
#include <cuda_runtime.h>
#include <cstdint>

// ---------------------------------------------------------------------------
// System2Reasoner: sim = P @ M^T, top-k(50) softmax(tau=0.02) message passing,
// l2norm update, evidence-softmax global feature.
//
//   K0 quant  : fp32 -> int8 (fixed scale 127/6, saturating), written PRE-TILED
//               and PRE-SWIZZLED (tile = 128 rows x 256 k, as 4 x 8KB blocks
//               byte-identical to the smem image)
//   K1 gemm   : PERSISTENT int8 IMMA m16n8k32. 288 co-resident CTAs
//               (16 m-tiles x 18 n-slices); A tile loaded once, B tiles
//               streamed through a 2-stage cp.async.bulk ring (producer one
//               tile ahead). Fused per-row top-2-per-64-col extraction.
//   K2 merge  : per patch row: threshold candidates (window 3.2), exact fp32
//               rescore, exact softmax, message, l2norm -> updated rows
//   K3 G1/G2  : evidence softmax over 2048 rows, partial weighted sums
//               (128 CTAs) then reduce + l2norm (1 CTA)
//
// NOTE: tcgen05 unusable (harness ptxas target sm_100, no 'a' suffix).
// ---------------------------------------------------------------------------

#define M_PATCH 2048
#define N_MEM   100000
#define D_DIM   256
#define INV_TAU 50.0f

#define BM 128
#define BN 128
#define N_PAD 100096                        // 782 * 128
#define NT_M (M_PATCH / BM)                 // 16
#define NT_N (N_PAD / BN)                   // 782
#define SLICES 18                           // n-slices (16*18=288 CTAs, all resident)
#define NCH  (N_PAD / 64)                   // 1564 chunks of 64 columns
#define TOPC 2
#define TILE_BYTES 32768                    // 128 rows x 256 k int8

#define QSCALE 21.166666f                   // 127/6
#define DEQ    0.0022320040f                // (6/127)^2
#define WINDOW 3.2f

#define PARTS 128

// dynamic smem: A tile 32KB + 2 B stages x 32KB
#define SM_ALLOC 98304

// -------------------- device scratch (static, no allocs) -------------------
__device__ int8_t g_memT[(size_t)NT_N * TILE_BYTES];     // pre-tiled B
__device__ int8_t g_patchT[(size_t)NT_M * TILE_BYTES];   // pre-tiled A
__device__ float g_cval[(size_t)M_PATCH * NCH * TOPC];
__device__ int   g_cidx[(size_t)M_PATCH * NCH * TOPC];
__device__ float g_evidence[M_PATCH];
__device__ float g_part[PARTS * D_DIM];

// -------------------- PTX helpers ------------------------------------------
__device__ __forceinline__ unsigned smem_u32(const void* p) {
    return (unsigned)__cvta_generic_to_shared(p);
}
__device__ __forceinline__ void cp_bulk(unsigned dst, const void* src,
                                        unsigned bytes, unsigned mbar) {
    asm volatile(
        "cp.async.bulk.shared::cluster.global.mbarrier::complete_tx::bytes "
        "[%0], [%1], %2, [%3];"
        :: "r"(dst), "l"(src), "r"(bytes), "r"(mbar) : "memory");
}
#define MBARRIER_INIT(mbar, cnt) \
    asm volatile("mbarrier.init.shared.b64 [%0], %1;" \
                 :: "r"((uint32_t)(mbar)), "r"((uint32_t)(cnt)) : "memory")
#define MBARRIER_EXPECT_TX(mbar, bytes) \
    asm volatile("mbarrier.arrive.expect_tx.shared.b64 _, [%0], %1;" \
                 :: "r"((uint32_t)(mbar)), "r"((uint32_t)(bytes)) : "memory")
__device__ __forceinline__ void mbar_wait_parity(uint32_t mbar, uint32_t parity) {
    uint32_t done;
    asm volatile(
        "{\n\t.reg .pred p;\n\t"
        "mbarrier.try_wait.parity.acquire.cta.shared::cta.b64 p, [%1], %2;\n\t"
        "selp.b32 %0, 1, 0, p;\n\t}"
        : "=r"(done) : "r"(mbar), "r"(parity) : "memory");
    if (!done) {
        asm volatile(
            "{\n\t.reg .pred P1;\n\t"
            "WAIT_LOOP_%=:\n\t"
            "mbarrier.try_wait.parity.acquire.cta.shared::cta.b64 P1, [%0], %1, 0x989680;\n\t"
            "@P1 bra.uni WAIT_DONE_%=;\n\t"
            "bra.uni WAIT_LOOP_%=;\n\t"
            "WAIT_DONE_%=:\n\t}"
            :: "r"(mbar), "r"(parity) : "memory");
    }
}

__device__ __forceinline__ void ldmatrix_x4(unsigned* d, unsigned addr) {
    asm volatile("ldmatrix.sync.aligned.m8n8.x4.shared.b16 {%0,%1,%2,%3}, [%4];\n"
                 : "=r"(d[0]), "=r"(d[1]), "=r"(d[2]), "=r"(d[3]) : "r"(addr));
}
// int8 IMMA: D(s32 16x8) += A(s8 16x32) * B(s8 32x8)
__device__ __forceinline__ void imma16832(int* c, const unsigned* a, const unsigned* b) {
    asm volatile(
        "mma.sync.aligned.m16n8k32.row.col.s32.s8.s8.s32 "
        "{%0,%1,%2,%3}, {%4,%5,%6,%7}, {%8,%9}, {%0,%1,%2,%3};\n"
        : "+r"(c[0]), "+r"(c[1]), "+r"(c[2]), "+r"(c[3])
        : "r"(a[0]), "r"(a[1]), "r"(a[2]), "r"(a[3]), "r"(b[0]), "r"(b[1]));
}

// swizzled byte offset within an 8KB block: row (0..127) of 64B, 16B chunk c
__device__ __forceinline__ unsigned swz(int row, int c) {
    return (unsigned)(row * 64 + ((c ^ ((row >> 1) & 3)) << 4));
}

// deterministic block reductions (fixed tree), 256 threads
__device__ __forceinline__ float block_max256(float v, float* s) {
    int t = threadIdx.x;
    s[t] = v; __syncthreads();
    #pragma unroll
    for (int off = 128; off > 0; off >>= 1) {
        if (t < off) s[t] = fmaxf(s[t], s[t + off]);
        __syncthreads();
    }
    float r = s[0]; __syncthreads();
    return r;
}
__device__ __forceinline__ float block_sum256(float v, float* s) {
    int t = threadIdx.x;
    s[t] = v; __syncthreads();
    #pragma unroll
    for (int off = 128; off > 0; off >>= 1) {
        if (t < off) s[t] = s[t] + s[t + off];
        __syncthreads();
    }
    float r = s[0]; __syncthreads();
    return r;
}

// -------------------- K0: fp32 -> int8, pre-tiled + pre-swizzled ------------
__device__ __forceinline__ int8_t q8(float x) {
    float v = fminf(fmaxf(x * QSCALE, -127.0f), 127.0f);
    return (int8_t)__float2int_rn(v);
}
__device__ __forceinline__ uint32_t q8x4(float4 v) {
    uint8_t b0 = (uint8_t)q8(v.x), b1 = (uint8_t)q8(v.y);
    uint8_t b2 = (uint8_t)q8(v.z), b3 = (uint8_t)q8(v.w);
    return (uint32_t)b0 | ((uint32_t)b1 << 8) | ((uint32_t)b2 << 16) | ((uint32_t)b3 << 24);
}
__global__ void quant_kernel(const float* __restrict__ patches,
                             const float* __restrict__ mem) {
    size_t stride = (size_t)gridDim.x * blockDim.x;
    size_t i0 = (size_t)blockIdx.x * blockDim.x + threadIdx.x;

    const size_t nB = (size_t)N_PAD * 16;          // 16 chunks per 256-elem row
    for (size_t i = i0; i < nB; i += stride) {
        int n = (int)(i >> 4), w = (int)(i & 15);
        int kc = w >> 2, c = w & 3;
        uint4 o = make_uint4(0, 0, 0, 0);
        if (n < N_MEM) {
            const float4* src = (const float4*)&mem[(size_t)n * D_DIM + w * 16];
            o.x = q8x4(src[0]); o.y = q8x4(src[1]);
            o.z = q8x4(src[2]); o.w = q8x4(src[3]);
        }
        size_t dst = (size_t)(n >> 7) * TILE_BYTES + kc * 8192 + swz(n & 127, c);
        *(uint4*)&g_memT[dst] = o;
    }
    const size_t nA = (size_t)M_PATCH * 16;
    for (size_t i = i0; i < nA; i += stride) {
        int m = (int)(i >> 4), w = (int)(i & 15);
        int kc = w >> 2, c = w & 3;
        const float4* src = (const float4*)&patches[(size_t)m * D_DIM + w * 16];
        uint4 o;
        o.x = q8x4(src[0]); o.y = q8x4(src[1]);
        o.z = q8x4(src[2]); o.w = q8x4(src[3]);
        size_t dst = (size_t)(m >> 7) * TILE_BYTES + kc * 8192 + swz(m & 127, c);
        *(uint4*)&g_patchT[dst] = o;
    }
}

// -------------------- K1: persistent int8 GEMM + fused top-2/64 -------------
// grid (NT_M, SLICES), 256 threads (8 warps: 4 M-quadrants x 2 N-halves),
// warp tile 32 (M) x 64 (N), K = 256. A resident; B double-buffered ring.
__global__ void __launch_bounds__(256, 2)
gemm_topk_i8() {
    extern __shared__ char smem_raw[];
    const unsigned sa  = smem_u32(smem_raw);            // A: 32KB
    const unsigned sB[2] = { sa + 32768, sa + 65536 };  // B stages
    __shared__ alignas(8) unsigned long long mbars[3];  // A, B0, B1
    const unsigned mbA = smem_u32(&mbars[0]);
    const unsigned mbB[2] = { smem_u32(&mbars[1]), smem_u32(&mbars[2]) };

    const int tid = threadIdx.x;
    const int warp = tid >> 5, lane = tid & 31;
    const int wx = warp >> 1, wy = warp & 1;
    const int g = lane >> 2, t = lane & 3;
    const int m0 = blockIdx.x * BM;
    const int sl = blockIdx.y;
    const int cnt = 43 + (sl < 8 ? 1 : 0);
    const int t0 = sl * 43 + min(sl, 8);

    if (tid == 0) {
        MBARRIER_INIT(mbA, 1); MBARRIER_INIT(mbB[0], 1); MBARRIER_INIT(mbB[1], 1);
    }
    __syncthreads();
    if (tid == 0) {
        MBARRIER_EXPECT_TX(mbA, TILE_BYTES);
        cp_bulk(sa, &g_patchT[(size_t)blockIdx.x * TILE_BYTES], TILE_BYTES, mbA);
        MBARRIER_EXPECT_TX(mbB[0], TILE_BYTES);
        cp_bulk(sB[0], &g_memT[(size_t)t0 * TILE_BYTES], TILE_BYTES, mbB[0]);
    }
    mbar_wait_parity(mbA, 0);

    for (int it = 0; it < cnt; ++it) {
        const int nt = t0 + it;
        const int n0 = nt * BN;
        // producer: one tile ahead (stage freed by syncthreads at end of it-1)
        if (tid == 0 && it + 1 < cnt) {
            MBARRIER_EXPECT_TX(mbB[(it + 1) & 1], TILE_BYTES);
            cp_bulk(sB[(it + 1) & 1], &g_memT[(size_t)(nt + 1) * TILE_BYTES],
                    TILE_BYTES, mbB[(it + 1) & 1]);
        }
        mbar_wait_parity(mbB[it & 1], (it >> 1) & 1);
        const unsigned sbb = sB[it & 1];

        int acc[2][8][4];
        #pragma unroll
        for (int a = 0; a < 2; ++a)
            #pragma unroll
            for (int b = 0; b < 8; ++b)
                #pragma unroll
                for (int c = 0; c < 4; ++c) acc[a][b][c] = 0;

        #pragma unroll
        for (int kc = 0; kc < 4; ++kc) {
            #pragma unroll
            for (int kk = 0; kk < 2; ++kk) {          // two k=32 steps
                unsigned afrag[2][4];
                #pragma unroll
                for (int mm = 0; mm < 2; ++mm) {
                    int r = wx * 32 + mm * 16 + (lane & 15);
                    int c = kk * 2 + (lane >> 4);
                    ldmatrix_x4(afrag[mm], sa + kc * 8192 + swz(r, c));
                }
                unsigned bfrag[8][2];
                #pragma unroll
                for (int jp = 0; jp < 4; ++jp) {
                    int r = wy * 64 + jp * 16 + (lane & 7) + ((lane >> 4) << 3);
                    int c = kk * 2 + ((lane >> 3) & 1);
                    unsigned q[4];
                    ldmatrix_x4(q, sbb + kc * 8192 + swz(r, c));
                    bfrag[2 * jp][0]     = q[0]; bfrag[2 * jp][1]     = q[1];
                    bfrag[2 * jp + 1][0] = q[2]; bfrag[2 * jp + 1][1] = q[3];
                }
                #pragma unroll
                for (int mm = 0; mm < 2; ++mm)
                    #pragma unroll
                    for (int j = 0; j < 8; ++j)
                        imma16832(acc[mm][j], afrag[mm], bfrag[j]);
            }
        }

        // ---- epilogue: per-row top-2 over this warp's 64 columns ----
        #pragma unroll
        for (int mm = 0; mm < 2; ++mm) {
            #pragma unroll
            for (int half = 0; half < 2; ++half) {
                float v0 = -INFINITY, v1 = -INFINITY;
                int   i0 = -1, i1 = -1;
                #pragma unroll
                for (int j = 0; j < 8; ++j) {
                    #pragma unroll
                    for (int c2 = 0; c2 < 2; ++c2) {
                        int col = n0 + wy * 64 + j * 8 + t * 2 + c2;
                        float v = (col < N_MEM)
                                  ? (float)acc[mm][j][half * 2 + c2] * DEQ
                                  : -INFINITY;
                        if (v > v0)      { v1 = v0; i1 = i0; v0 = v; i0 = col; }
                        else if (v > v1) { v1 = v;  i1 = col; }
                    }
                }
                #pragma unroll
                for (int off = 1; off <= 2; off <<= 1) {
                    float u0 = __shfl_xor_sync(0xffffffffu, v0, off);
                    int  ui0 = __shfl_xor_sync(0xffffffffu, i0, off);
                    float u1 = __shfl_xor_sync(0xffffffffu, v1, off);
                    int  ui1 = __shfl_xor_sync(0xffffffffu, i1, off);
                    if (u0 > v0) {
                        float s = v0; int si = i0;
                        v0 = u0; i0 = ui0;
                        if (u1 > s) { s = u1; si = ui1; }
                        v1 = s; i1 = si;
                    } else if (u0 > v1) { v1 = u0; i1 = ui0; }
                }
                if (t == 0) {
                    int grow  = m0 + wx * 32 + mm * 16 + g + half * 8;
                    int chunk = nt * 2 + wy;
                    size_t base = ((size_t)grow * NCH + chunk) * TOPC;
                    *(float2*)&g_cval[base] = make_float2(v0, v1);
                    *(int2*)&g_cidx[base]   = make_int2(i0, i1);
                }
            }
        }
        __syncthreads();   // stage (it&1) free for refill at it+1
    }
}

// -------------------- K2: merge + exact rescore + update --------------------
// one CTA (256 threads) per patch row
__global__ void __launch_bounds__(256)
merge_kernel(const float* __restrict__ patches,
             const float* __restrict__ mem,
             float* __restrict__ out) {
    const int row = blockIdx.x;
    const int tid = threadIdx.x;

    __shared__ float s_patch[D_DIM];
    __shared__ float s_red[256];
    __shared__ int   s_cnt[256];
    __shared__ int   s_sel[256];
    __shared__ float s_val[256];

    s_patch[tid] = patches[(size_t)row * D_DIM + tid];

    const float* cv = &g_cval[(size_t)row * NCH * TOPC];
    const int*   ci = &g_cidx[(size_t)row * NCH * TOPC];
    const int NC = NCH * TOPC;                       // 3128

    float mx = -INFINITY;
    for (int i = tid; i < NC; i += 256) mx = fmaxf(mx, cv[i]);
    float amax = block_max256(mx, s_red);
    float thr = amax - WINDOW;

    int c = 0;
    for (int i = tid; i < NC; i += 256) if (cv[i] >= thr) c++;
    s_cnt[tid] = c; __syncthreads();
    for (int off = 1; off < 256; off <<= 1) {
        int v = (tid >= off) ? s_cnt[tid - off] : 0;
        __syncthreads();
        s_cnt[tid] += v;
        __syncthreads();
    }
    int total = s_cnt[255];
    int base = s_cnt[tid] - c;
    int nsel = min(total, 256);
    int o = base;
    for (int i = tid; i < NC; i += 256)
        if (cv[i] >= thr) { if (o < 256) s_sel[o] = ci[i]; o++; }
    __syncthreads();

    const int warp = tid >> 5, lane = tid & 31;
    for (int cs = warp; cs < nsel; cs += 8) {
        const float* mrow = mem + (size_t)s_sel[cs] * D_DIM;
        float ssum = 0.0f;
        #pragma unroll
        for (int d = lane; d < D_DIM; d += 32) ssum += mrow[d] * s_patch[d];
        #pragma unroll
        for (int off = 16; off > 0; off >>= 1)
            ssum += __shfl_xor_sync(0xffffffffu, ssum, off);
        if (lane == 0) s_val[cs] = ssum;
    }
    __syncthreads();

    float vmx = -INFINITY;
    for (int i = tid; i < nsel; i += 256) vmx = fmaxf(vmx, s_val[i]);
    float vmax = block_max256(vmx, s_red);

    float zs = 0.0f;
    for (int i = tid; i < nsel; i += 256) {
        float w = expf((s_val[i] - vmax) * INV_TAU);
        s_val[i] = w;
        zs += w;
    }
    __syncthreads();
    float Z = block_sum256(zs, s_red);
    float Zinv = 1.0f / Z;

    float m = 0.0f;
    for (int cs = 0; cs < nsel; ++cs) {
        float w = s_val[cs];
        if (w > 0.0f) m += w * mem[(size_t)s_sel[cs] * D_DIM + tid];
    }
    float upd = s_patch[tid] + m * Zinv;

    float n2 = block_sum256(upd * upd, s_red);
    upd = upd / fmaxf(sqrtf(n2), 1e-12f);
    out[D_DIM + (size_t)row * D_DIM + tid] = upd;
    if (tid == 0) g_evidence[row] = vmax;
}

// -------------------- K3: global feature (two-phase, deterministic) ---------
__global__ void __launch_bounds__(256)
global_partial_kernel(const float* __restrict__ out) {
    __shared__ float s_red[256];
    const int tid = threadIdx.x;
    const int r0 = blockIdx.x * (M_PATCH / PARTS);

    float mx = -INFINITY;
    for (int i = tid; i < M_PATCH; i += 256) mx = fmaxf(mx, g_evidence[i]);
    float emax = block_max256(mx, s_red);

    float zs = 0.0f;
    for (int i = tid; i < M_PATCH; i += 256) zs += expf((g_evidence[i] - emax) * INV_TAU);
    float Z = block_sum256(zs, s_red);
    float Zinv = 1.0f / Z;

    float acc = 0.0f;
    #pragma unroll
    for (int r = 0; r < M_PATCH / PARTS; ++r) {
        int i = r0 + r;
        float w = expf((g_evidence[i] - emax) * INV_TAU);
        if (w > 0.0f) acc += w * out[D_DIM + (size_t)i * D_DIM + tid];
    }
    g_part[blockIdx.x * D_DIM + tid] = acc * Zinv;
}

__global__ void __launch_bounds__(256)
global_reduce_kernel(float* __restrict__ out) {
    __shared__ float s_red[256];
    const int tid = threadIdx.x;
    float acc = 0.0f;
    #pragma unroll
    for (int c = 0; c < PARTS; ++c) acc += g_part[c * D_DIM + tid];
    float n2 = block_sum256(acc * acc, s_red);
    out[tid] = acc / fmaxf(sqrtf(n2), 1e-12f);
}

// -------------------- launcher ----------------------------------------------
extern "C" void kernel_launch(void* const* d_in, const int* in_sizes, int n_in,
                              void* d_out, int out_size) {
    const float* patches = (const float*)d_in[0];   // (2048, 256)
    const float* mem     = (const float*)d_in[1];   // (100000, 256)
    float* out = (float*)d_out;                     // [256 global | 2048*256 updated]

    cudaFuncSetAttribute(gemm_topk_i8, cudaFuncAttributeMaxDynamicSharedMemorySize,
                         SM_ALLOC);

    quant_kernel<<<2048, 256>>>(patches, mem);
    dim3 grid(NT_M, SLICES);
    gemm_topk_i8<<<grid, 256, SM_ALLOC>>>();
    merge_kernel<<<M_PATCH, 256>>>(patches, mem, out);
    global_partial_kernel<<<PARTS, 256>>>(out);
    global_reduce_kernel<<<1, 256>>>(out);
}

// round 6
// speedup vs baseline: 3.9417x; 1.6238x over previous
#include <cuda_runtime.h>
#include <cstdint>
#include <climits>

// ---------------------------------------------------------------------------
// System2Reasoner: sim = P @ M^T, top-k(50) softmax(tau=0.02) message passing,
// l2norm update, evidence-softmax global feature.
//
//   K0 quant  : fp32 -> int8 (fixed scale 127/6), PRE-TILED + PRE-SWIZZLED
//               (tile = 128 rows x 256 k as 4 x 8KB blocks == smem image),
//               1 thread per source row, 64B contiguous stores
//   K1 gemm   : PERSISTENT int8 IMMA m16n8k32 (288 co-resident CTAs, A tile
//               resident, B streamed via 2-stage cp.async.bulk ring).
//               Fused branchless per-row top-2-per-64-col extraction with
//               PACKED keys (acc<<6 | col) -> single output array.
//   K2 merge  : per patch row: threshold packed keys (int window), exact fp32
//               rescore, exact softmax, message, l2norm -> updated rows
//   K3 G1/G2  : evidence softmax over 2048 rows, partial weighted sums
//               (512 CTAs x 4 rows) then reduce + l2norm (1 CTA)
//
// NOTE: tcgen05 unusable (harness ptxas target sm_100, no 'a' suffix).
// mma.sync int8 measured at ~22cyc/instr/SMSP on sm_100 => GEMM ~280us floor.
// ---------------------------------------------------------------------------

#define M_PATCH 2048
#define N_MEM   100000
#define D_DIM   256
#define INV_TAU 50.0f

#define BM 128
#define BN 128
#define N_PAD 100096                        // 782 * 128
#define NT_M (M_PATCH / BM)                 // 16
#define NT_N (N_PAD / BN)                   // 782
#define SLICES 18                           // 16*18 = 288 CTAs, all resident
#define NCH  (N_PAD / 64)                   // 1564 chunks of 64 columns
#define TILE_BYTES 32768                    // 128 rows x 256 k int8

#define QSCALE 21.166666f                   // 127/6
// window 3.2 (sim units) in int-dot units: 3.2*(127/6)^2 = 1433.7 -> 1434
#define WINDOW_KEY (1434 << 6)

#define PARTS 512

// dynamic smem: A tile 32KB + 2 B stages x 32KB
#define SM_ALLOC 98304

// -------------------- device scratch (static, no allocs) -------------------
__device__ int8_t g_memT[(size_t)NT_N * TILE_BYTES];     // pre-tiled B
__device__ int8_t g_patchT[(size_t)NT_M * TILE_BYTES];   // pre-tiled A
__device__ int   g_ckey[(size_t)M_PATCH * NCH * 2];      // packed (acc<<6|col6)
__device__ float g_evidence[M_PATCH];
__device__ float g_part[PARTS * D_DIM];

// -------------------- PTX helpers ------------------------------------------
__device__ __forceinline__ unsigned smem_u32(const void* p) {
    return (unsigned)__cvta_generic_to_shared(p);
}
__device__ __forceinline__ void cp_bulk(unsigned dst, const void* src,
                                        unsigned bytes, unsigned mbar) {
    asm volatile(
        "cp.async.bulk.shared::cluster.global.mbarrier::complete_tx::bytes "
        "[%0], [%1], %2, [%3];"
        :: "r"(dst), "l"(src), "r"(bytes), "r"(mbar) : "memory");
}
#define MBARRIER_INIT(mbar, cnt) \
    asm volatile("mbarrier.init.shared.b64 [%0], %1;" \
                 :: "r"((uint32_t)(mbar)), "r"((uint32_t)(cnt)) : "memory")
#define MBARRIER_EXPECT_TX(mbar, bytes) \
    asm volatile("mbarrier.arrive.expect_tx.shared.b64 _, [%0], %1;" \
                 :: "r"((uint32_t)(mbar)), "r"((uint32_t)(bytes)) : "memory")
__device__ __forceinline__ void mbar_wait_parity(uint32_t mbar, uint32_t parity) {
    uint32_t done;
    asm volatile(
        "{\n\t.reg .pred p;\n\t"
        "mbarrier.try_wait.parity.acquire.cta.shared::cta.b64 p, [%1], %2;\n\t"
        "selp.b32 %0, 1, 0, p;\n\t}"
        : "=r"(done) : "r"(mbar), "r"(parity) : "memory");
    if (!done) {
        asm volatile(
            "{\n\t.reg .pred P1;\n\t"
            "WAIT_LOOP_%=:\n\t"
            "mbarrier.try_wait.parity.acquire.cta.shared::cta.b64 P1, [%0], %1, 0x989680;\n\t"
            "@P1 bra.uni WAIT_DONE_%=;\n\t"
            "bra.uni WAIT_LOOP_%=;\n\t"
            "WAIT_DONE_%=:\n\t}"
            :: "r"(mbar), "r"(parity) : "memory");
    }
}

__device__ __forceinline__ void ldmatrix_x4(unsigned* d, unsigned addr) {
    asm volatile("ldmatrix.sync.aligned.m8n8.x4.shared.b16 {%0,%1,%2,%3}, [%4];\n"
                 : "=r"(d[0]), "=r"(d[1]), "=r"(d[2]), "=r"(d[3]) : "r"(addr));
}
// int8 IMMA: D(s32 16x8) += A(s8 16x32) * B(s8 32x8)
__device__ __forceinline__ void imma16832(int* c, const unsigned* a, const unsigned* b) {
    asm volatile(
        "mma.sync.aligned.m16n8k32.row.col.s32.s8.s8.s32 "
        "{%0,%1,%2,%3}, {%4,%5,%6,%7}, {%8,%9}, {%0,%1,%2,%3};\n"
        : "+r"(c[0]), "+r"(c[1]), "+r"(c[2]), "+r"(c[3])
        : "r"(a[0]), "r"(a[1]), "r"(a[2]), "r"(a[3]), "r"(b[0]), "r"(b[1]));
}

// swizzled byte offset within an 8KB block: row (0..127) of 64B, 16B chunk c
__device__ __forceinline__ unsigned swz(int row, int c) {
    return (unsigned)(row * 64 + ((c ^ ((row >> 1) & 3)) << 4));
}

// deterministic block reductions (fixed tree), 256 threads
__device__ __forceinline__ float block_max256(float v, float* s) {
    int t = threadIdx.x;
    s[t] = v; __syncthreads();
    #pragma unroll
    for (int off = 128; off > 0; off >>= 1) {
        if (t < off) s[t] = fmaxf(s[t], s[t + off]);
        __syncthreads();
    }
    float r = s[0]; __syncthreads();
    return r;
}
__device__ __forceinline__ float block_sum256(float v, float* s) {
    int t = threadIdx.x;
    s[t] = v; __syncthreads();
    #pragma unroll
    for (int off = 128; off > 0; off >>= 1) {
        if (t < off) s[t] = s[t] + s[t + off];
        __syncthreads();
    }
    float r = s[0]; __syncthreads();
    return r;
}
__device__ __forceinline__ int block_imax256(int v, int* s) {
    int t = threadIdx.x;
    s[t] = v; __syncthreads();
    #pragma unroll
    for (int off = 128; off > 0; off >>= 1) {
        if (t < off) s[t] = max(s[t], s[t + off]);
        __syncthreads();
    }
    int r = s[0]; __syncthreads();
    return r;
}

// -------------------- K0: fp32 -> int8, pre-tiled + pre-swizzled ------------
__device__ __forceinline__ int8_t q8(float x) {
    float v = fminf(fmaxf(x * QSCALE, -127.0f), 127.0f);
    return (int8_t)__float2int_rn(v);
}
__device__ __forceinline__ uint32_t q8x4(float4 v) {
    uint8_t b0 = (uint8_t)q8(v.x), b1 = (uint8_t)q8(v.y);
    uint8_t b2 = (uint8_t)q8(v.z), b3 = (uint8_t)q8(v.w);
    return (uint32_t)b0 | ((uint32_t)b1 << 8) | ((uint32_t)b2 << 16) | ((uint32_t)b3 << 24);
}
// one thread per source row: read 1KB fp32, write 4 x 64B contiguous int8
__global__ void quant_kernel(const float* __restrict__ patches,
                             const float* __restrict__ mem) {
    int stride = gridDim.x * blockDim.x;
    const int TOTAL = N_PAD + M_PATCH;
    for (int n = blockIdx.x * blockDim.x + threadIdx.x; n < TOTAL; n += stride) {
        const float* src;
        int8_t* dstT;
        int row, tile;
        if (n < N_PAD) {
            tile = n >> 7; row = n & 127; dstT = g_memT;
            src = (n < N_MEM) ? (mem + (size_t)n * D_DIM) : nullptr;
        } else {
            int m = n - N_PAD;
            tile = m >> 7; row = m & 127; dstT = g_patchT;
            src = patches + (size_t)m * D_DIM;
        }
        unsigned sw = (row >> 1) & 3;
        size_t base = (size_t)tile * TILE_BYTES + (unsigned)row * 64;
        #pragma unroll
        for (int kc = 0; kc < 4; ++kc) {
            #pragma unroll
            for (int c = 0; c < 4; ++c) {
                uint4 o = make_uint4(0, 0, 0, 0);
                if (src) {
                    const float4* s4 = (const float4*)(src + kc * 64 + c * 16);
                    o.x = q8x4(s4[0]); o.y = q8x4(s4[1]);
                    o.z = q8x4(s4[2]); o.w = q8x4(s4[3]);
                }
                *(uint4*)&dstT[base + kc * 8192 + ((c ^ sw) << 4)] = o;
            }
        }
    }
}

// -------------------- K1: persistent int8 GEMM + packed top-2/64 ------------
// grid (NT_M, SLICES), 256 threads (8 warps: 4 M-quadrants x 2 N-halves),
// warp tile 32 (M) x 64 (N), K = 256. A resident; B double-buffered ring.
__global__ void __launch_bounds__(256, 2)
gemm_topk_i8() {
    extern __shared__ char smem_raw[];
    const unsigned sa  = smem_u32(smem_raw);            // A: 32KB
    const unsigned sB[2] = { sa + 32768, sa + 65536 };  // B stages
    __shared__ alignas(8) unsigned long long mbars[3];  // A, B0, B1
    const unsigned mbA = smem_u32(&mbars[0]);
    const unsigned mbB[2] = { smem_u32(&mbars[1]), smem_u32(&mbars[2]) };

    const int tid = threadIdx.x;
    const int warp = tid >> 5, lane = tid & 31;
    const int wx = warp >> 1, wy = warp & 1;
    const int g = lane >> 2, t = lane & 3;
    const int m0 = blockIdx.x * BM;
    const int sl = blockIdx.y;
    const int cnt = 43 + (sl < 8 ? 1 : 0);
    const int t0 = sl * 43 + min(sl, 8);

    if (tid == 0) {
        MBARRIER_INIT(mbA, 1); MBARRIER_INIT(mbB[0], 1); MBARRIER_INIT(mbB[1], 1);
    }
    __syncthreads();
    if (tid == 0) {
        MBARRIER_EXPECT_TX(mbA, TILE_BYTES);
        cp_bulk(sa, &g_patchT[(size_t)blockIdx.x * TILE_BYTES], TILE_BYTES, mbA);
        MBARRIER_EXPECT_TX(mbB[0], TILE_BYTES);
        cp_bulk(sB[0], &g_memT[(size_t)t0 * TILE_BYTES], TILE_BYTES, mbB[0]);
    }
    mbar_wait_parity(mbA, 0);

    for (int it = 0; it < cnt; ++it) {
        const int nt = t0 + it;
        if (tid == 0 && it + 1 < cnt) {
            MBARRIER_EXPECT_TX(mbB[(it + 1) & 1], TILE_BYTES);
            cp_bulk(sB[(it + 1) & 1], &g_memT[(size_t)(nt + 1) * TILE_BYTES],
                    TILE_BYTES, mbB[(it + 1) & 1]);
        }
        mbar_wait_parity(mbB[it & 1], (it >> 1) & 1);
        const unsigned sbb = sB[it & 1];

        int acc[2][8][4];
        #pragma unroll
        for (int a = 0; a < 2; ++a)
            #pragma unroll
            for (int b = 0; b < 8; ++b)
                #pragma unroll
                for (int c = 0; c < 4; ++c) acc[a][b][c] = 0;

        #pragma unroll
        for (int kc = 0; kc < 4; ++kc) {
            #pragma unroll
            for (int kk = 0; kk < 2; ++kk) {          // two k=32 steps
                unsigned afrag[2][4];
                #pragma unroll
                for (int mm = 0; mm < 2; ++mm) {
                    int r = wx * 32 + mm * 16 + (lane & 15);
                    int c = kk * 2 + (lane >> 4);
                    ldmatrix_x4(afrag[mm], sa + kc * 8192 + swz(r, c));
                }
                unsigned bfrag[8][2];
                #pragma unroll
                for (int jp = 0; jp < 4; ++jp) {
                    int r = wy * 64 + jp * 16 + (lane & 7) + ((lane >> 4) << 3);
                    int c = kk * 2 + ((lane >> 3) & 1);
                    unsigned q[4];
                    ldmatrix_x4(q, sbb + kc * 8192 + swz(r, c));
                    bfrag[2 * jp][0]     = q[0]; bfrag[2 * jp][1]     = q[1];
                    bfrag[2 * jp + 1][0] = q[2]; bfrag[2 * jp + 1][1] = q[3];
                }
                #pragma unroll
                for (int mm = 0; mm < 2; ++mm)
                    #pragma unroll
                    for (int j = 0; j < 8; ++j)
                        imma16832(acc[mm][j], afrag[mm], bfrag[j]);
            }
        }

        // ---- epilogue: branchless packed top-2 over this warp's 64 cols ----
        // key = (acc << 6) | local_col  (|acc| < 2^22, so no overflow; ties
        // break toward higher col — harmless, survivors are exactly rescored)
        #pragma unroll
        for (int mm = 0; mm < 2; ++mm) {
            #pragma unroll
            for (int half = 0; half < 2; ++half) {
                int v0 = INT_MIN, v1 = INT_MIN;
                #pragma unroll
                for (int j = 0; j < 8; ++j) {
                    #pragma unroll
                    for (int c2 = 0; c2 < 2; ++c2) {
                        int loc = j * 8 + t * 2 + c2;
                        int key = (acc[mm][j][half * 2 + c2] << 6) | loc;
                        v1 = max(v1, min(v0, key));
                        v0 = max(v0, key);
                    }
                }
                #pragma unroll
                for (int off = 1; off <= 2; off <<= 1) {
                    int u0 = __shfl_xor_sync(0xffffffffu, v0, off);
                    int u1 = __shfl_xor_sync(0xffffffffu, v1, off);
                    v1 = max(max(v1, u1), min(v0, u0));
                    v0 = max(v0, u0);
                }
                if (t == 0) {
                    int grow  = m0 + wx * 32 + mm * 16 + g + half * 8;
                    int chunk = nt * 2 + wy;
                    *(int2*)&g_ckey[((size_t)grow * NCH + chunk) * 2] =
                        make_int2(v0, v1);
                }
            }
        }
        __syncthreads();   // stage (it&1) free for refill at it+1
    }
}

// -------------------- K2: merge + exact rescore + update --------------------
// one CTA (256 threads) per patch row
__global__ void __launch_bounds__(256)
merge_kernel(const float* __restrict__ patches,
             const float* __restrict__ mem,
             float* __restrict__ out) {
    const int row = blockIdx.x;
    const int tid = threadIdx.x;

    __shared__ float s_patch[D_DIM];
    __shared__ float s_red[256];
    __shared__ int   s_cnt[256];
    __shared__ int   s_slot[256 * 4];
    __shared__ int   s_sel[256];
    __shared__ float s_val[256];

    s_patch[tid] = patches[(size_t)row * D_DIM + tid];

    const int2* ck = (const int2*)&g_ckey[(size_t)row * NCH * 2];

    // pass 1: max packed key (v0 components suffice: v0 >= v1 by construction)
    int mx = INT_MIN;
    for (int c = tid; c < NCH; c += 256) mx = max(mx, ck[c].x);
    int amax = block_imax256(mx, s_cnt);
    int thr = amax - WINDOW_KEY;

    // pass 2: threshold + per-thread slots (deterministic)
    int cnt = 0;
    for (int c = tid; c < NCH; c += 256) {
        int2 k2 = ck[c];
        if (k2.x >= thr && cnt < 4) s_slot[tid * 4 + cnt++] = c * 64 + (k2.x & 63);
        if (k2.y >= thr && cnt < 4) s_slot[tid * 4 + cnt++] = c * 64 + (k2.y & 63);
    }
    s_cnt[tid] = cnt; __syncthreads();
    for (int off = 1; off < 256; off <<= 1) {
        int v = (tid >= off) ? s_cnt[tid - off] : 0;
        __syncthreads();
        s_cnt[tid] += v;
        __syncthreads();
    }
    int total = s_cnt[255];
    int base = s_cnt[tid] - cnt;
    int nsel = min(total, 256);
    for (int q = 0; q < cnt; ++q) {
        int o = base + q;
        if (o < 256) s_sel[o] = s_slot[tid * 4 + q];
    }
    __syncthreads();

    // exact fp32 rescore of selected candidates
    const int warp = tid >> 5, lane = tid & 31;
    for (int cs = warp; cs < nsel; cs += 8) {
        const float* mrow = mem + (size_t)s_sel[cs] * D_DIM;
        float ssum = 0.0f;
        #pragma unroll
        for (int d = lane; d < D_DIM; d += 32) ssum += mrow[d] * s_patch[d];
        #pragma unroll
        for (int off = 16; off > 0; off >>= 1)
            ssum += __shfl_xor_sync(0xffffffffu, ssum, off);
        if (lane == 0) s_val[cs] = ssum;
    }
    __syncthreads();

    // exact max (evidence) and softmax weights
    float vmx = -INFINITY;
    for (int i = tid; i < nsel; i += 256) vmx = fmaxf(vmx, s_val[i]);
    float vmax = block_max256(vmx, s_red);

    float zs = 0.0f;
    for (int i = tid; i < nsel; i += 256) {
        float w = expf((s_val[i] - vmax) * INV_TAU);
        s_val[i] = w;
        zs += w;
    }
    __syncthreads();
    float Z = block_sum256(zs, s_red);
    float Zinv = 1.0f / Z;

    // message for dimension tid
    float m = 0.0f;
    for (int cs = 0; cs < nsel; ++cs) {
        float w = s_val[cs];
        if (w > 0.0f) m += w * mem[(size_t)s_sel[cs] * D_DIM + tid];
    }
    float upd = s_patch[tid] + m * Zinv;

    float n2 = block_sum256(upd * upd, s_red);
    upd = upd / fmaxf(sqrtf(n2), 1e-12f);
    out[D_DIM + (size_t)row * D_DIM + tid] = upd;
    if (tid == 0) g_evidence[row] = vmax;
}

// -------------------- K3: global feature (two-phase, deterministic) ---------
__global__ void __launch_bounds__(256)
global_partial_kernel(const float* __restrict__ out) {
    __shared__ float s_red[256];
    const int tid = threadIdx.x;
    const int r0 = blockIdx.x * (M_PATCH / PARTS);

    float mx = -INFINITY;
    for (int i = tid; i < M_PATCH; i += 256) mx = fmaxf(mx, g_evidence[i]);
    float emax = block_max256(mx, s_red);

    float zs = 0.0f;
    for (int i = tid; i < M_PATCH; i += 256) zs += expf((g_evidence[i] - emax) * INV_TAU);
    float Z = block_sum256(zs, s_red);
    float Zinv = 1.0f / Z;

    float acc = 0.0f;
    #pragma unroll
    for (int r = 0; r < M_PATCH / PARTS; ++r) {
        int i = r0 + r;
        float w = expf((g_evidence[i] - emax) * INV_TAU);
        if (w > 0.0f) acc += w * out[D_DIM + (size_t)i * D_DIM + tid];
    }
    g_part[blockIdx.x * D_DIM + tid] = acc * Zinv;
}

__global__ void __launch_bounds__(256)
global_reduce_kernel(float* __restrict__ out) {
    __shared__ float s_red[256];
    const int tid = threadIdx.x;
    float acc = 0.0f;
    for (int c = 0; c < PARTS; ++c) acc += g_part[c * D_DIM + tid];
    float n2 = block_sum256(acc * acc, s_red);
    out[tid] = acc / fmaxf(sqrtf(n2), 1e-12f);
}

// -------------------- launcher ----------------------------------------------
extern "C" void kernel_launch(void* const* d_in, const int* in_sizes, int n_in,
                              void* d_out, int out_size) {
    const float* patches = (const float*)d_in[0];   // (2048, 256)
    const float* mem     = (const float*)d_in[1];   // (100000, 256)
    float* out = (float*)d_out;                     // [256 global | 2048*256 updated]

    cudaFuncSetAttribute(gemm_topk_i8, cudaFuncAttributeMaxDynamicSharedMemorySize,
                         SM_ALLOC);

    quant_kernel<<<512, 256>>>(patches, mem);
    dim3 grid(NT_M, SLICES);
    gemm_topk_i8<<<grid, 256, SM_ALLOC>>>();
    merge_kernel<<<M_PATCH, 256>>>(patches, mem, out);
    global_partial_kernel<<<PARTS, 256>>>(out);
    global_reduce_kernel<<<1, 256>>>(out);
}